// round 16
// baseline (speedup 1.0000x reference)
#include <cuda_runtime.h>
#include <cuda_fp16.h>
#include <math.h>
#include <stdint.h>

#define DIM   1024
#define NH    8
#define SEQ   2048
#define BATCH 2
#define NTOK  (BATCH*SEQ)
#define QC    128
#define KVC   128
#define KROPE 64
#define VHD   256
#define HD    128
#define EPSV  1e-8f
#define SCALE_ATT 0.08838834764831845f

// ---------------- scratch (static device globals; no allocations) ------------
__device__ __half g_wdh[1024*320];
__device__ __half g_wuqh[128*1024];
__device__ __half g_wkvh[128*2560];
__device__ __half g_cqh[NTOK*QC];
__device__ __half g_ckvh[NTOK*KVC];
__device__ __half g_qh [(size_t)BATCH*NH*SEQ*HD];   // prescaled q, fp16
__device__ __half g_kh [(size_t)BATCH*NH*SEQ*HD];
__device__ __half g_ah [(size_t)NTOK*NH*KVC];        // U = probs.ckv
__device__ __half g_woh[(size_t)(NH*VHD)*DIM];
__device__ __half g_w2h[(size_t)(NH*KVC)*DIM];       // W2 = stack_h(Wuv_h @ wo_h)
__device__ float  g_bf [DIM];                         // fused bias

// ---------------- mma / ldmatrix / cp.async helpers --------------------------
__device__ __forceinline__ uint32_t smem_u32(const void* p){
    uint32_t a;
    asm("{ .reg .u64 t; cvta.to.shared.u64 t, %1; cvt.u32.u64 %0, t; }"
        : "=r"(a) : "l"(p));
    return a;
}
__device__ __forceinline__ void ldsm_x4(uint32_t& d0, uint32_t& d1,
                                        uint32_t& d2, uint32_t& d3, uint32_t addr){
    asm volatile("ldmatrix.sync.aligned.m8n8.x4.shared.b16 {%0,%1,%2,%3}, [%4];"
        : "=r"(d0), "=r"(d1), "=r"(d2), "=r"(d3) : "r"(addr));
}
__device__ __forceinline__ void ldsm_x4_t(uint32_t& d0, uint32_t& d1,
                                          uint32_t& d2, uint32_t& d3, uint32_t addr){
    asm volatile("ldmatrix.sync.aligned.m8n8.x4.trans.shared.b16 {%0,%1,%2,%3}, [%4];"
        : "=r"(d0), "=r"(d1), "=r"(d2), "=r"(d3) : "r"(addr));
}
__device__ __forceinline__ void mma_f16(float* c, const uint32_t* a,
                                        uint32_t b0, uint32_t b1){
    asm volatile(
        "mma.sync.aligned.m16n8k16.row.col.f32.f16.f16.f32 "
        "{%0,%1,%2,%3}, {%4,%5,%6,%7}, {%8,%9}, {%0,%1,%2,%3};"
        : "+f"(c[0]), "+f"(c[1]), "+f"(c[2]), "+f"(c[3])
        : "r"(a[0]), "r"(a[1]), "r"(a[2]), "r"(a[3]), "r"(b0), "r"(b1));
}
#define CP_ASYNC16(dst, src) \
    asm volatile("cp.async.cg.shared.global [%0], [%1], 16;" \
        :: "r"(dst), "l"(src) : "memory")
#define CP_ASYNC_COMMIT() asm volatile("cp.async.commit_group;" ::: "memory")
#define CP_ASYNC_WAIT1()  asm volatile("cp.async.wait_group 1;" ::: "memory")
#define CP_ASYNC_WAIT0()  asm volatile("cp.async.wait_group 0;" ::: "memory")

__device__ __forceinline__ uint32_t pack2h(float a, float b){
    __half2 t = __floats2half2_rn(a, b);
    return *reinterpret_cast<uint32_t*>(&t);
}

// ================= kprep: all weight conversions + fused bias, one kernel ===
// blocks [0,1280): wd pack; [1280,1408): wuq; [1408,1728): wkv;
// [1728,3776): wo; [3776,3808): bfuse.
__global__ __launch_bounds__(256) void kprep(
    const float* __restrict__ wdq, const float* __restrict__ wdkv,
    const float* __restrict__ wuq, const float* __restrict__ wkv,
    const float* __restrict__ wo,  const float* __restrict__ bkv,
    const float* __restrict__ bo)
{
    __shared__ float red[8][32];
    const int b = blockIdx.x, tid = threadIdx.x;
    if (b < 1280) {
        int i = b*256 + tid;
        int k = i / 320, j = i - k*320;
        float v = (j < 128) ? wdq[k*128 + j] : wdkv[k*192 + (j-128)];
        g_wdh[i] = __float2half_rn(v);
    } else if (b < 1408) {
        int i = ((b-1280)*256 + tid) * 4;
        float4 v = *(const float4*)(wuq + i);
        *(uint2*)(g_wuqh + i) = make_uint2(pack2h(v.x, v.y), pack2h(v.z, v.w));
    } else if (b < 1728) {
        int i = ((b-1408)*256 + tid) * 4;
        float4 v = *(const float4*)(wkv + i);
        *(uint2*)(g_wkvh + i) = make_uint2(pack2h(v.x, v.y), pack2h(v.z, v.w));
    } else if (b < 3776) {
        int i = ((b-1728)*256 + tid) * 4;
        float4 v = *(const float4*)(wo + i);
        *(uint2*)(g_woh + i) = make_uint2(pack2h(v.x, v.y), pack2h(v.z, v.w));
    } else {
        const int cl = tid & 31, jl = tid >> 5;
        const int c = (b-3776) * 32 + cl;
        float s = 0.f;
#pragma unroll 4
        for (int j = jl; j < NH*VHD; j += 8)
            s += bkv[512 + j] * wo[(size_t)j*DIM + c];
        red[jl][cl] = s;
        __syncthreads();
        if (jl == 0) {
            float t = bo[c];
#pragma unroll
            for (int u = 0; u < 8; u++) t += red[u][cl];
            g_bf[c] = t;
        }
    }
}

// ================= k1g: x @ Wd, cp.async-pipelined + rmsnorm + k-rope =======
// grid 128 (32 tokens/CTA), 256 threads (8 warps: 2m x 4n[80]).
// smem: A bufs 2 x (32x80B) at 0/2560; B bufs 2 x (32x656B) at 5120/26112.
#define SA1B(buf) ((uint32_t)(buf)*2560u)
#define SB1B(buf) (5120u + (uint32_t)(buf)*20992u)
#define K1_SMEM 47104u
#define STG_STR 324   // floats

__global__ __launch_bounds__(256) void k1g(
    const float* __restrict__ x, const int* __restrict__ pos,
    const float* __restrict__ bdq, const float* __restrict__ bdkv,
    const float* __restrict__ qnw, const float* __restrict__ kvnw)
{
    extern __shared__ char smem[];
    const uint32_t sb = smem_u32(smem);
    const int tid = threadIdx.x, lane = tid & 31, wid = tid >> 5;
    const int t0 = blockIdx.x * 32;
    const int wm = wid & 1, wn = wid >> 1;

    float o[10][4];
#pragma unroll
    for (int i = 0; i < 10; i++) { o[i][0]=0.f;o[i][1]=0.f;o[i][2]=0.f;o[i][3]=0.f; }

    const uint32_t aA = (uint32_t)((wm*16 + (lane & 15))*80 + (lane >> 4)*16);
    const uint32_t bB_r = (uint32_t)((lane & 7) + (((lane >> 3) & 1) << 3));
    const uint32_t bB_cb = (uint32_t)(((lane >> 4) << 4));
    const int arow = tid >> 3, ac = tid & 7;   // A loader: 32 rows x 8 float4

    // ---- prologue: tile 0 (B via cp.async, A via regular cvt store) ----
    {
#pragma unroll
        for (int t = 0; t < 5; t++) {
            int i = tid + t*256;
            int row = i / 40, c = i - row*40;
            CP_ASYNC16(sb + SB1B(0) + row*656 + c*16,
                       g_wdh + (size_t)row*320 + c*8);
        }
        CP_ASYNC_COMMIT();
        float4 v = *(const float4*)(x + (size_t)(t0+arow)*DIM + ac*4);
        *(uint2*)(smem + SA1B(0) + arow*80 + ac*8) =
            make_uint2(pack2h(v.x, v.y), pack2h(v.z, v.w));
    }

    for (int ks = 0; ks < 32; ks++) {
        const uint32_t cur = (uint32_t)(ks & 1);
        if (ks + 1 < 32) {
            const int kn = (ks + 1) * 32;
            // issue A global load early so it overlaps the async issue
            float4 av = *(const float4*)(x + (size_t)(t0+arow)*DIM + kn + ac*4);
#pragma unroll
            for (int t = 0; t < 5; t++) {
                int i = tid + t*256;
                int row = i / 40, c = i - row*40;
                CP_ASYNC16(sb + SB1B(cur^1u) + row*656 + c*16,
                           g_wdh + (size_t)(kn+row)*320 + c*8);
            }
            CP_ASYNC_COMMIT();
            *(uint2*)(smem + SA1B(cur^1u) + arow*80 + ac*8) =
                make_uint2(pack2h(av.x, av.y), pack2h(av.z, av.w));
            CP_ASYNC_WAIT1();
        } else {
            CP_ASYNC_WAIT0();
        }
        __syncthreads();

        const uint32_t abase = sb + SA1B(cur);
        const uint32_t bbase = sb + SB1B(cur);
#pragma unroll
        for (int kb = 0; kb < 2; kb++) {
            uint32_t a[4];
            ldsm_x4(a[0],a[1],a[2],a[3], abase + aA + kb*32);
#pragma unroll
            for (int nf2 = 0; nf2 < 5; nf2++) {
                uint32_t cb = (uint32_t)((wn*80 + nf2*16)*2) + bB_cb;
                uint32_t rb = (uint32_t)((kb*16 + bB_r)*656);
                uint32_t b[4];
                ldsm_x4_t(b[0],b[1],b[2],b[3], bbase + rb + cb);
                mma_f16(o[2*nf2],   a, b[0], b[1]);
                mma_f16(o[2*nf2+1], a, b[2], b[3]);
            }
        }
        __syncthreads();
    }

    float* sacc = (float*)smem;
    {
        int r0 = wm*16 + (lane >> 2);
#pragma unroll
        for (int nf = 0; nf < 10; nf++) {
            int j = wn*80 + nf*8 + (lane & 3)*2;
            float b0 = (j < 128) ? bdq[j]   : bdkv[j-128];
            float b1 = (j+1 < 128) ? bdq[j+1] : bdkv[j+1-128];
            sacc[r0*STG_STR + j]       = o[nf][0] + b0;
            sacc[r0*STG_STR + j + 1]   = o[nf][1] + b1;
            sacc[(r0+8)*STG_STR + j]   = o[nf][2] + b0;
            sacc[(r0+8)*STG_STR + j+1] = o[nf][3] + b1;
        }
    }
    __syncthreads();

    const int row = tid >> 3, chunk = tid & 7;
    const float* rp = sacc + row*STG_STR;
    float s1 = 0.f, s2 = 0.f;
#pragma unroll
    for (int u = 0; u < 16; u++) {
        float a = rp[chunk*16 + u];       s1 += a*a;
        float b = rp[128 + chunk*16 + u]; s2 += b*b;
    }
#pragma unroll
    for (int m = 4; m >= 1; m >>= 1) {
        s1 += __shfl_xor_sync(0xffffffffu, s1, m);
        s2 += __shfl_xor_sync(0xffffffffu, s2, m);
    }
    float inv1 = rsqrtf(s1 * (1.f/128.f) + EPSV);
    float inv2 = rsqrtf(s2 * (1.f/128.f) + EPSV);

    {
        uint32_t oh[8];
#pragma unroll
        for (int u = 0; u < 8; u++) {
            int j = chunk*16 + 2*u;
            oh[u] = pack2h(rp[j] * inv1 * qnw[j], rp[j+1] * inv1 * qnw[j+1]);
        }
        *(uint4*)(g_cqh + (size_t)(t0+row)*QC + chunk*16)     = *(uint4*)oh;
        *(uint4*)(g_cqh + (size_t)(t0+row)*QC + chunk*16 + 8) = *(uint4*)(oh+4);
#pragma unroll
        for (int u = 0; u < 8; u++) {
            int j = chunk*16 + 2*u;
            oh[u] = pack2h(rp[128+j] * inv2 * kvnw[j], rp[128+j+1] * inv2 * kvnw[j+1]);
        }
        *(uint4*)(g_ckvh + (size_t)(t0+row)*KVC + chunk*16)     = *(uint4*)oh;
        *(uint4*)(g_ckvh + (size_t)(t0+row)*KVC + chunk*16 + 8) = *(uint4*)(oh+4);
    }
    {
        int tg = t0 + row; int bbg = tg >> 11; int sg = tg & (SEQ-1);
        float posf = (float)pos[tg];
        uint32_t oh[4];
#pragma unroll
        for (int q = 0; q < 4; q++) {
            int p = chunk*4 + q;
            float inv_freq = powf(10000.f, -(float)(2*p)/64.f);
            float sn, cs; sincosf(posf * inv_freq, &sn, &cs);
            float xe = rp[256 + 2*p], xo = rp[256 + 2*p + 1];
            oh[q] = pack2h(xe*cs - xo*sn, xe*sn + xo*cs);
        }
#pragma unroll
        for (int h = 0; h < NH; h++) {
            size_t off = (((size_t)bbg*NH + h)*SEQ + sg)*HD + 64 + chunk*8;
            *(uint4*)(g_kh + off) = *(uint4*)oh;
        }
    }
}

// ================= k2g: cq @ wuq (fp16 HMMA) + rope -> g_qh fp16 prescaled ==
#define SA2 0u
#define SB2 17408u
#define K2_SMEM 52224u

__global__ __launch_bounds__(256, 2) void k2g(
    const int* __restrict__ pos, const float* __restrict__ buq)
{
    extern __shared__ char smem[];
    const uint32_t sb = smem_u32(smem);
    const int tid = threadIdx.x, lane = tid & 31, wid = tid >> 5;
    const int t0 = blockIdx.x * 64, n0 = blockIdx.y * 128;
    const int wm = wid & 1, wn = wid >> 1;

#pragma unroll
    for (int t = 0; t < 4; t++) {
        int i = tid + t*256;
        int row = i >> 4, c = i & 15;
        *(uint4*)(smem + SA2 + row*272 + c*16) =
            *(const uint4*)(g_cqh + (size_t)(t0+row)*QC + c*8);
    }
#pragma unroll
    for (int t = 0; t < 8; t++) {
        int i = tid + t*256;
        int row = i >> 4, c = i & 15;
        *(uint4*)(smem + SB2 + row*272 + c*16) =
            *(const uint4*)(g_wuqh + (size_t)row*1024 + n0 + c*8);
    }
    __syncthreads();

    float o[2][4][4];
#pragma unroll
    for (int i = 0; i < 2; i++)
#pragma unroll
        for (int j = 0; j < 4; j++)
            { o[i][j][0]=0.f;o[i][j][1]=0.f;o[i][j][2]=0.f;o[i][j][3]=0.f; }

    const uint32_t bB_r = (uint32_t)((lane & 7) + (((lane >> 3) & 1) << 3));
    const uint32_t bB_cb = (uint32_t)((lane >> 4) << 4);

#pragma unroll
    for (int kb = 0; kb < 8; kb++) {
        uint32_t a[2][4];
#pragma unroll
        for (int mf = 0; mf < 2; mf++) {
            uint32_t ad = (uint32_t)((wm*32 + mf*16 + (lane&15))*272 + kb*32 + ((lane>>4)<<4));
            ldsm_x4(a[mf][0],a[mf][1],a[mf][2],a[mf][3], sb + SA2 + ad);
        }
#pragma unroll
        for (int nf2 = 0; nf2 < 2; nf2++) {
            uint32_t cb = (uint32_t)((wn*32 + nf2*16)*2) + bB_cb;
            uint32_t rb = (uint32_t)((kb*16 + bB_r)*272);
            uint32_t b[4];
            ldsm_x4_t(b[0],b[1],b[2],b[3], sb + SB2 + rb + cb);
#pragma unroll
            for (int mf = 0; mf < 2; mf++) {
                mma_f16(o[mf][2*nf2],   a[mf], b[0], b[1]);
                mma_f16(o[mf][2*nf2+1], a[mf], b[2], b[3]);
            }
        }
    }

#pragma unroll
    for (int mf = 0; mf < 2; mf++) {
#pragma unroll
        for (int nf = 0; nf < 4; nf++) {
            int j = n0 + wn*32 + nf*8 + (lane & 3)*2;
            float b0 = buq[j], b1 = buq[j+1];
            float v0 = (o[mf][nf][0] + b0) * SCALE_ATT, v1 = (o[mf][nf][1] + b1) * SCALE_ATT;
            float v2 = (o[mf][nf][2] + b0) * SCALE_ATT, v3 = (o[mf][nf][3] + b1) * SCALE_ATT;
            int ta = t0 + wm*32 + mf*16 + (lane >> 2);
            int tb = ta + 8;
            if (j < 768) {
                int h = j / 96, d = j - h*96;
                int bba = ta >> 11, sa = ta & (SEQ-1);
                int bbb = tb >> 11, sbt = tb & (SEQ-1);
                *(uint32_t*)(g_qh + (((size_t)bba*NH + h)*SEQ + sa)*HD + d)  = pack2h(v0, v1);
                *(uint32_t*)(g_qh + (((size_t)bbb*NH + h)*SEQ + sbt)*HD + d) = pack2h(v2, v3);
            } else {
                int r = j - 768;
                int h = r >> 5, rpv = r & 31, p = rpv >> 1;
                float inv_freq = powf(10000.f, -(float)(2*p)/32.f);
                int d = 96 + rpv;
                int bba = ta >> 11, sa = ta & (SEQ-1);
                int bbb = tb >> 11, sbt = tb & (SEQ-1);
                float sn, cs;
                sincosf((float)pos[ta] * inv_freq, &sn, &cs);
                *(uint32_t*)(g_qh + (((size_t)bba*NH + h)*SEQ + sa)*HD + d) =
                    pack2h(v0*cs - v1*sn, v0*sn + v1*cs);
                sincosf((float)pos[tb] * inv_freq, &sn, &cs);
                *(uint32_t*)(g_qh + (((size_t)bbb*NH + h)*SEQ + sbt)*HD + d) =
                    pack2h(v2*cs - v3*sn, v2*sn + v3*cs);
            }
        }
    }
}

// ================= k3g: ckv @ wuk (fp16 HMMA) -> k_nope fp16 ================
__global__ __launch_bounds__(256, 2) void k3g(const float* __restrict__ bkv)
{
    extern __shared__ char smem[];
    const uint32_t sb = smem_u32(smem);
    const int tid = threadIdx.x, lane = tid & 31, wid = tid >> 5;
    const int t0 = blockIdx.x * 64, n0 = blockIdx.y * 128;
    const int wm = wid & 1, wn = wid >> 1;

#pragma unroll
    for (int t = 0; t < 4; t++) {
        int i = tid + t*256;
        int row = i >> 4, c = i & 15;
        *(uint4*)(smem + SA2 + row*272 + c*16) =
            *(const uint4*)(g_ckvh + (size_t)(t0+row)*KVC + c*8);
    }
#pragma unroll
    for (int t = 0; t < 8; t++) {
        int i = tid + t*256;
        int row = i >> 4, c = i & 15;
        *(uint4*)(smem + SB2 + row*272 + c*16) =
            *(const uint4*)(g_wkvh + (size_t)row*2560 + n0 + c*8);
    }
    __syncthreads();

    float o[2][4][4];
#pragma unroll
    for (int i = 0; i < 2; i++)
#pragma unroll
        for (int j = 0; j < 4; j++)
            { o[i][j][0]=0.f;o[i][j][1]=0.f;o[i][j][2]=0.f;o[i][j][3]=0.f; }

    const uint32_t bB_r = (uint32_t)((lane & 7) + (((lane >> 3) & 1) << 3));
    const uint32_t bB_cb = (uint32_t)((lane >> 4) << 4);

#pragma unroll
    for (int kb = 0; kb < 8; kb++) {
        uint32_t a[2][4];
#pragma unroll
        for (int mf = 0; mf < 2; mf++) {
            uint32_t ad = (uint32_t)((wm*32 + mf*16 + (lane&15))*272 + kb*32 + ((lane>>4)<<4));
            ldsm_x4(a[mf][0],a[mf][1],a[mf][2],a[mf][3], sb + SA2 + ad);
        }
#pragma unroll
        for (int nf2 = 0; nf2 < 2; nf2++) {
            uint32_t cb = (uint32_t)((wn*32 + nf2*16)*2) + bB_cb;
            uint32_t rb = (uint32_t)((kb*16 + bB_r)*272);
            uint32_t b[4];
            ldsm_x4_t(b[0],b[1],b[2],b[3], sb + SB2 + rb + cb);
#pragma unroll
            for (int mf = 0; mf < 2; mf++) {
                mma_f16(o[mf][2*nf2],   a[mf], b[0], b[1]);
                mma_f16(o[mf][2*nf2+1], a[mf], b[2], b[3]);
            }
        }
    }

#pragma unroll
    for (int mf = 0; mf < 2; mf++) {
#pragma unroll
        for (int nf = 0; nf < 4; nf++) {
            int j = n0 + wn*32 + nf*8 + (lane & 3)*2;   // < 512
            float b0 = bkv[j], b1 = bkv[j+1];
            int h = j >> 6, d = j & 63;
            int ta = t0 + wm*32 + mf*16 + (lane >> 2);
            int tb = ta + 8;
            int bba = ta >> 11, sa = ta & (SEQ-1);
            int bbb = tb >> 11, sbt = tb & (SEQ-1);
            *(uint32_t*)(g_kh + (((size_t)bba*NH + h)*SEQ + sa)*HD + d) =
                pack2h(o[mf][nf][0] + b0, o[mf][nf][1] + b1);
            *(uint32_t*)(g_kh + (((size_t)bbb*NH + h)*SEQ + sbt)*HD + d) =
                pack2h(o[mf][nf][2] + b0, o[mf][nf][3] + b1);
        }
    }
}

// ================= kW2: W2_h = Wuv_h @ wo_h (single-pass fp16) ==============
#define W2ASTR 80
#define W2BSTR 272
#define W2_A 0u
#define W2_B (W2_A + 128u*W2ASTR)
#define KW2_SMEM (W2_B + 32u*W2BSTR)   // 18944

__global__ __launch_bounds__(256, 2) void kW2()
{
    extern __shared__ char smem[];
    const uint32_t sb = smem_u32(smem);
    const int tid = threadIdx.x, lane = tid & 31, wid = tid >> 5;
    const int n0 = blockIdx.x * 128, hh = blockIdx.y;
    const int wm = wid & 3, wn = wid >> 2;

    float o[2][8][4];
#pragma unroll
    for (int i = 0; i < 2; i++)
#pragma unroll
        for (int j = 0; j < 8; j++)
            { o[i][j][0]=0.f; o[i][j][1]=0.f; o[i][j][2]=0.f; o[i][j][3]=0.f; }

    const uint32_t aA_r = (uint32_t)(wm*32 + (lane & 15));
    const uint32_t aA_c = (uint32_t)((lane >> 4) * 16);
    const uint32_t bB_r = (uint32_t)((lane & 7) + (((lane >> 3) & 1) << 3));
    const uint32_t bB_c = (uint32_t)(wn*128 + ((lane >> 4) << 4));

    for (int k0 = 0; k0 < VHD; k0 += 32) {
        {
#pragma unroll
            for (int t = 0; t < 2; t++) {
                int i = tid + t*256;
                int row = i >> 2, c = i & 3;
                *(uint4*)(smem + W2_A + row*W2ASTR + c*16) =
                    *(const uint4*)(g_wkvh + (size_t)row*2560 + 512 + hh*VHD + k0 + c*8);
            }
#pragma unroll
            for (int t = 0; t < 2; t++) {
                int i = tid + t*256;
                int row = i >> 4, c = i & 15;
                *(uint4*)(smem + W2_B + row*W2BSTR + c*16) =
                    *(const uint4*)(g_woh + (size_t)(hh*VHD + k0 + row)*DIM + n0 + c*8);
            }
        }
        __syncthreads();

#pragma unroll
        for (int kb = 0; kb < 2; kb++) {
            uint32_t a[2][4];
            ldsm_x4(a[0][0],a[0][1],a[0][2],a[0][3],
                    sb + W2_A + aA_r*W2ASTR + kb*32 + aA_c);
            ldsm_x4(a[1][0],a[1][1],a[1][2],a[1][3],
                    sb + W2_A + (aA_r+16)*W2ASTR + kb*32 + aA_c);
#pragma unroll
            for (int vfp = 0; vfp < 4; vfp++) {
                uint32_t b[4];
                ldsm_x4_t(b[0],b[1],b[2],b[3],
                          sb + W2_B + (kb*16 + bB_r)*W2BSTR + vfp*32 + bB_c);
                mma_f16(o[0][2*vfp],   a[0], b[0], b[1]);
                mma_f16(o[0][2*vfp+1], a[0], b[2], b[3]);
                mma_f16(o[1][2*vfp],   a[1], b[0], b[1]);
                mma_f16(o[1][2*vfp+1], a[1], b[2], b[3]);
            }
        }
        __syncthreads();
    }

#pragma unroll
    for (int mf = 0; mf < 2; mf++) {
        int rbase = wm*32 + mf*16 + (lane >> 2);
#pragma unroll
        for (int nf = 0; nf < 8; nf++) {
            int col = n0 + wn*64 + nf*8 + (lane & 3)*2;
            *(uint32_t*)(g_w2h + (size_t)(hh*KVC + rbase)*DIM + col) =
                pack2h(o[mf][nf][0], o[mf][nf][1]);
            *(uint32_t*)(g_w2h + (size_t)(hh*KVC + rbase + 8)*DIM + col) =
                pack2h(o[mf][nf][2], o[mf][nf][3]);
        }
    }
}

// ================= Kernel 4: flash attention, absorbed V, double-buffered ===
// grid (16, 16 bh), 256 threads. smem: Q 128x272, K[2] 64x272, C[2] 64x272.
#define K4_SMQ 0u
#define K4_SMK 34816u    // + buf*17408
#define K4_SMC 69632u    // + buf*17408
#define K4_SMEM 104448u

__global__ __launch_bounds__(256, 2) void k4_attn_mma()
{
    extern __shared__ char smem[];
    const uint32_t sb = smem_u32(smem);
    const int tid = threadIdx.x, lane = tid & 31, wid = tid >> 5;
    const int bh = blockIdx.y, q0 = blockIdx.x * 128;
    const int bb = bh >> 3, h = bh & 7;

    // stage Q (prescaled fp16) via regular loads
    {
        const uint4* Qg = (const uint4*)(g_qh + ((size_t)bh*SEQ + q0)*HD);
#pragma unroll
        for (int t = 0; t < 8; t++) {
            int i = tid + t*256;
            int row = i >> 4, c = i & 15;
            *(uint4*)(smem + K4_SMQ + row*272 + c*16) = Qg[i];
        }
    }
    // prefetch tile 0 into buffer 0
    {
        const __half* Kg = g_kh + ((size_t)bh*SEQ)*HD;
        const __half* Cg = g_ckvh + ((size_t)bb*SEQ)*KVC;
#pragma unroll
        for (int t = 0; t < 4; t++) {
            int i = tid + t*256;
            int row = i >> 4, c = i & 15;
            CP_ASYNC16(sb + K4_SMK + row*272 + c*16, Kg + (size_t)row*HD + c*8);
            CP_ASYNC16(sb + K4_SMC + row*272 + c*16, Cg + (size_t)row*KVC + c*8);
        }
        CP_ASYNC_COMMIT();
    }

    float o[16][4];
#pragma unroll
    for (int i = 0; i < 16; i++) { o[i][0]=0.f; o[i][1]=0.f; o[i][2]=0.f; o[i][3]=0.f; }
    float ls0 = 0.f, ls1 = 0.f;

    const uint32_t aQ_r = (uint32_t)(wid*16 + (lane & 15));
    const uint32_t aQ_c = (uint32_t)((lane >> 4) * 16);
    const uint32_t bK_r = (uint32_t)((lane & 7) + ((lane >> 4) << 3));
    const uint32_t bK_c = (uint32_t)(((lane >> 3) & 1) << 4);
    const uint32_t bV_r = (uint32_t)((lane & 7) + (((lane >> 3) & 1) << 3));
    const uint32_t bV_c = (uint32_t)((lane >> 4) << 4);

    for (int kt = 0; kt < SEQ/64; ++kt) {
        const uint32_t cur = (uint32_t)(kt & 1);
        if (kt + 1 < SEQ/64) {
            const __half* Kg = g_kh + ((size_t)bh*SEQ + (size_t)(kt+1)*64)*HD;
            const __half* Cg = g_ckvh + ((size_t)bb*SEQ + (size_t)(kt+1)*64)*KVC;
            const uint32_t nb = (cur ^ 1u) * 17408u;
#pragma unroll
            for (int t = 0; t < 4; t++) {
                int i = tid + t*256;
                int row = i >> 4, c = i & 15;
                CP_ASYNC16(sb + K4_SMK + nb + row*272 + c*16, Kg + (size_t)row*HD + c*8);
                CP_ASYNC16(sb + K4_SMC + nb + row*272 + c*16, Cg + (size_t)row*KVC + c*8);
            }
            CP_ASYNC_COMMIT();
            CP_ASYNC_WAIT1();
        } else {
            CP_ASYNC_WAIT0();
        }
        __syncthreads();

        const uint32_t kbase = sb + K4_SMK + cur*17408u;
        const uint32_t cbase = sb + K4_SMC + cur*17408u;

        float s[8][4];
#pragma unroll
        for (int i = 0; i < 8; i++) { s[i][0]=0.f; s[i][1]=0.f; s[i][2]=0.f; s[i][3]=0.f; }
#pragma unroll
        for (int kb = 0; kb < 8; kb++) {
            uint32_t a[4];
            ldsm_x4(a[0],a[1],a[2],a[3], sb + K4_SMQ + aQ_r*272 + kb*32 + aQ_c);
#pragma unroll
            for (int nfp = 0; nfp < 4; nfp++) {
                uint32_t b[4];
                ldsm_x4(b[0],b[1],b[2],b[3],
                        kbase + (nfp*16 + bK_r)*272 + kb*32 + bK_c);
                mma_f16(s[2*nfp],   a, b[0], b[1]);
                mma_f16(s[2*nfp+1], a, b[2], b[3]);
            }
        }

        uint32_t pa[4][4];
#pragma unroll
        for (int nf = 0; nf < 8; nf++) {
            float p0 = __expf(s[nf][0]), p1 = __expf(s[nf][1]);
            float p2 = __expf(s[nf][2]), p3 = __expf(s[nf][3]);
            ls0 += p0 + p1; ls1 += p2 + p3;
            int kb2 = nf >> 1;
            if ((nf & 1) == 0) { pa[kb2][0] = pack2h(p0,p1); pa[kb2][1] = pack2h(p2,p3); }
            else               { pa[kb2][2] = pack2h(p0,p1); pa[kb2][3] = pack2h(p2,p3); }
        }

#pragma unroll
        for (int vfp = 0; vfp < 8; vfp++) {
#pragma unroll
            for (int kb = 0; kb < 4; kb++) {
                uint32_t b[4];
                ldsm_x4_t(b[0],b[1],b[2],b[3],
                          cbase + (kb*16 + bV_r)*272 + vfp*32 + bV_c);
                mma_f16(o[2*vfp],   pa[kb], b[0], b[1]);
                mma_f16(o[2*vfp+1], pa[kb], b[2], b[3]);
            }
        }
        __syncthreads();
    }

    ls0 += __shfl_xor_sync(0xffffffffu, ls0, 1);
    ls0 += __shfl_xor_sync(0xffffffffu, ls0, 2);
    ls1 += __shfl_xor_sync(0xffffffffu, ls1, 1);
    ls1 += __shfl_xor_sync(0xffffffffu, ls1, 2);
    float inv0 = 1.f / ls0, inv1 = 1.f / ls1;

    const int r0 = q0 + wid*16 + (lane >> 2);
    const size_t off0 = (size_t)(bb*SEQ + r0)*(NH*KVC) + h*KVC + (lane & 3)*2;
    const size_t off1 = off0 + (size_t)8*(NH*KVC);
#pragma unroll
    for (int vf = 0; vf < 16; vf++) {
        *(uint32_t*)(g_ah + off0 + vf*8) = pack2h(o[vf][0]*inv0, o[vf][1]*inv0);
        *(uint32_t*)(g_ah + off1 + vf*8) = pack2h(o[vf][2]*inv1, o[vf][3]*inv1);
    }
}

// ================= Kernel 5: out = U[4096,1024] @ W2[1024,1024] + bfuse =====
#define ASTR 80
#define BSTR 272
#define SM5_A 0u
#define SM5_B (SM5_A + 128u*ASTR)
#define K5_SMEM (SM5_B + 32u*BSTR)   // 18944 bytes

__global__ __launch_bounds__(256, 2) void k5_oproj_mma(float* __restrict__ out)
{
    extern __shared__ char smem[];
    const uint32_t sb = smem_u32(smem);
    const int tid = threadIdx.x, lane = tid & 31, wid = tid >> 5;
    const int m0 = blockIdx.x * 128, n0 = blockIdx.y * 128;
    const int wm = wid & 3, wn = wid >> 2;

    float o[2][8][4];
#pragma unroll
    for (int i = 0; i < 2; i++)
#pragma unroll
        for (int j = 0; j < 8; j++)
            { o[i][j][0]=0.f; o[i][j][1]=0.f; o[i][j][2]=0.f; o[i][j][3]=0.f; }

    const uint32_t aA_r = (uint32_t)(wm*32 + (lane & 15));
    const uint32_t aA_c = (uint32_t)((lane >> 4) * 16);
    const uint32_t bB_r = (uint32_t)((lane & 7) + (((lane >> 3) & 1) << 3));
    const uint32_t bB_c = (uint32_t)(wn*128 + ((lane >> 4) << 4));

    for (int k0 = 0; k0 < NH*KVC; k0 += 32) {
        {
            const uint4* Ah = (const uint4*)(g_ah + (size_t)m0*(NH*KVC) + k0);
#pragma unroll
            for (int t = 0; t < 2; t++) {
                int i = tid + t*256;
                int row = i >> 2, c = i & 3;
                *(uint4*)(smem + SM5_A + row*ASTR + c*16) = Ah[(size_t)row*128 + c];
            }
            const uint4* Bh = (const uint4*)(g_w2h + (size_t)k0*DIM + n0);
#pragma unroll
            for (int t = 0; t < 2; t++) {
                int i = tid + t*256;
                int row = i >> 4, c = i & 15;
                *(uint4*)(smem + SM5_B + row*BSTR + c*16) = Bh[(size_t)row*128 + c];
            }
        }
        __syncthreads();

#pragma unroll
        for (int kb = 0; kb < 2; kb++) {
            uint32_t a[2][4];
            ldsm_x4(a[0][0],a[0][1],a[0][2],a[0][3],
                    sb + SM5_A + aA_r*ASTR + kb*32 + aA_c);
            ldsm_x4(a[1][0],a[1][1],a[1][2],a[1][3],
                    sb + SM5_A + (aA_r+16)*ASTR + kb*32 + aA_c);
#pragma unroll
            for (int vfp = 0; vfp < 4; vfp++) {
                uint32_t b[4];
                ldsm_x4_t(b[0],b[1],b[2],b[3],
                          sb + SM5_B + (kb*16 + bB_r)*BSTR + vfp*32 + bB_c);
                mma_f16(o[0][2*vfp],   a[0], b[0], b[1]);
                mma_f16(o[0][2*vfp+1], a[0], b[2], b[3]);
                mma_f16(o[1][2*vfp],   a[1], b[0], b[1]);
                mma_f16(o[1][2*vfp+1], a[1], b[2], b[3]);
            }
        }
        __syncthreads();
    }

#pragma unroll
    for (int mf = 0; mf < 2; mf++) {
        int rbase = m0 + wm*32 + mf*16 + (lane >> 2);
#pragma unroll
        for (int nf = 0; nf < 8; nf++) {
            int col = n0 + wn*64 + nf*8 + (lane & 3)*2;
            float b0 = g_bf[col], b1 = g_bf[col+1];
            float2 v0 = make_float2(o[mf][nf][0] + b0, o[mf][nf][1] + b1);
            float2 v1 = make_float2(o[mf][nf][2] + b0, o[mf][nf][3] + b1);
            *(float2*)(out + (size_t)rbase*DIM + col)     = v0;
            *(float2*)(out + (size_t)(rbase+8)*DIM + col) = v1;
        }
    }
}

// ============================================================================
extern "C" void kernel_launch(void* const* d_in, const int* in_sizes, int n_in,
                              void* d_out, int out_size)
{
    const float* x    = (const float*)d_in[0];
    const int*   pos  = (const int*)  d_in[1];
    const float* wdq  = (const float*)d_in[2];
    const float* bdq  = (const float*)d_in[3];
    const float* qnw  = (const float*)d_in[4];
    const float* wuq  = (const float*)d_in[5];
    const float* buq  = (const float*)d_in[6];
    const float* wdkv = (const float*)d_in[7];
    const float* bdkv = (const float*)d_in[8];
    const float* kvnw = (const float*)d_in[9];
    const float* wkv  = (const float*)d_in[10];
    const float* bkv  = (const float*)d_in[11];
    const float* wo   = (const float*)d_in[12];
    const float* bo   = (const float*)d_in[13];
    float* out = (float*)d_out;

    cudaFuncSetAttribute(k1g,          cudaFuncAttributeMaxDynamicSharedMemorySize, K1_SMEM);
    cudaFuncSetAttribute(k2g,          cudaFuncAttributeMaxDynamicSharedMemorySize, K2_SMEM);
    cudaFuncSetAttribute(k3g,          cudaFuncAttributeMaxDynamicSharedMemorySize, K2_SMEM);
    cudaFuncSetAttribute(kW2,          cudaFuncAttributeMaxDynamicSharedMemorySize, KW2_SMEM);
    cudaFuncSetAttribute(k4_attn_mma,  cudaFuncAttributeMaxDynamicSharedMemorySize, K4_SMEM);
    cudaFuncSetAttribute(k5_oproj_mma, cudaFuncAttributeMaxDynamicSharedMemorySize, K5_SMEM);

    kprep<<<3808, 256>>>(wdq, wdkv, wuq, wkv, wo, bkv, bo);
    kW2<<<dim3(8, 8), 256, KW2_SMEM>>>();

    k1g<<<NTOK/32, 256, K1_SMEM>>>(x, pos, bdq, bdkv, qnw, kvnw);
    k2g<<<dim3(NTOK/64, 8), 256, K2_SMEM>>>(pos, buq);
    k3g<<<dim3(NTOK/64, 4), 256, K2_SMEM>>>(bkv);
    k4_attn_mma<<<dim3(SEQ/128, BATCH*NH), 256, K4_SMEM>>>();
    k5_oproj_mma<<<dim3(NTOK/128, DIM/128), 256, K5_SMEM>>>(out);
}